// round 3
// baseline (speedup 1.0000x reference)
#include <cuda_runtime.h>
#include <cstdint>

#define N_NODES 100000
#define N_EDGES 3200000
#define F0 16
#define F1 32
#define F2 3

// ---------------- scratch (no allocations allowed) ----------------
__device__ int g_is64;                                  // 1 if edge_index is int64
__device__ static int   g_src[N_EDGES];
__device__ static int   g_dst[N_EDGES];
__device__ __align__(16) static float g_deg [N_NODES];
__device__ __align__(16) static float g_dinv[N_NODES];
__device__ __align__(16) static float g_h1s [N_NODES * F1]; // h1 * dinv, pre-scaled
__device__ __align__(16) static float g_agg1[N_NODES * F1];
__device__ __align__(16) static float g_h2s [N_NODES * F2];
__device__ __align__(16) static float g_agg2[N_NODES * F2];

// ---------------- dtype detect + convert ----------------

// int64 node ids < 2^31  => odd 32-bit words are all zero.
// int32 random ids in [0,100000) => odd words ~never all zero over 128 samples.
__global__ void k_detect(const int* __restrict__ ei32) {
    if (threadIdx.x == 0) {
        int any_nonzero = 0;
        for (int k = 0; k < 128; k++)
            any_nonzero |= ei32[2 * k + 1];
        g_is64 = (any_nonzero == 0) ? 1 : 0;
    }
}

__global__ void k_convert(const void* __restrict__ ei) {
    int e = blockIdx.x * blockDim.x + threadIdx.x;
    if (e >= N_EDGES) return;
    if (g_is64) {
        const long long* p = (const long long*)ei;
        g_src[e] = (int)p[e];
        g_dst[e] = (int)p[N_EDGES + e];
    } else {
        const int* p = (const int*)ei;
        g_src[e] = p[e];
        g_dst[e] = p[N_EDGES + e];
    }
}

// ---------------- kernels ----------------

__global__ void k_init_deg() {
    int i = blockIdx.x * blockDim.x + threadIdx.x;
    if (i < N_NODES) g_deg[i] = 1.0f;  // self-loop
}

__global__ void k_count_deg() {
    int e = blockIdx.x * blockDim.x + threadIdx.x;
    if (e < N_EDGES)
        atomicAdd(&g_deg[g_dst[e]], 1.0f);  // result unused -> RED
}

__global__ void k_dinv() {
    int i = blockIdx.x * blockDim.x + threadIdx.x;
    if (i < N_NODES) g_dinv[i] = rsqrtf(g_deg[i]);
}

// h1 = x @ W1 ; h1s = h1*dinv ; agg1 init = h1s*dinv (self-loop term)
__global__ void k_layer1_node(const float* __restrict__ x,
                              const float* __restrict__ W1) {
    __shared__ float sW[F0 * F1];
    for (int t = threadIdx.x; t < F0 * F1; t += blockDim.x) sW[t] = W1[t];
    __syncthreads();

    int i = blockIdx.x * blockDim.x + threadIdx.x;
    if (i >= N_NODES) return;

    float xv[F0];
    const float4* xr = (const float4*)(x + i * F0);
    #pragma unroll
    for (int k = 0; k < F0 / 4; k++) {
        float4 v = xr[k];
        xv[4*k+0] = v.x; xv[4*k+1] = v.y; xv[4*k+2] = v.z; xv[4*k+3] = v.w;
    }

    float acc[F1];
    #pragma unroll
    for (int j = 0; j < F1; j++) acc[j] = 0.0f;
    #pragma unroll
    for (int k = 0; k < F0; k++) {
        float xk = xv[k];
        #pragma unroll
        for (int j = 0; j < F1; j++) acc[j] = fmaf(xk, sW[k * F1 + j], acc[j]);
    }

    float di = g_dinv[i];
    float4* h1s  = (float4*)(g_h1s  + i * F1);
    float4* agg1 = (float4*)(g_agg1 + i * F1);
    #pragma unroll
    for (int j = 0; j < F1 / 4; j++) {
        float4 s, a;
        s.x = acc[4*j+0] * di; s.y = acc[4*j+1] * di;
        s.z = acc[4*j+2] * di; s.w = acc[4*j+3] * di;
        a.x = s.x * di; a.y = s.y * di; a.z = s.z * di; a.w = s.w * di;
        h1s[j]  = s;
        agg1[j] = a;
    }
}

__device__ __forceinline__ void red_add_v4(float* p, float a, float b, float c, float d) {
    asm volatile(
        "{\n\t"
        ".reg .u64 pg;\n\t"
        "cvta.to.global.u64 pg, %0;\n\t"
        "red.global.add.v4.f32 [pg], {%1, %2, %3, %4};\n\t"
        "}"
        :: "l"(p), "f"(a), "f"(b), "f"(c), "f"(d)
        : "memory");
}

// 8 lanes per edge: lane owns one float4 slice of the 32-feature message
__global__ void k_edge1() {
    unsigned tid = blockIdx.x * blockDim.x + threadIdx.x;
    unsigned e = tid >> 3;
    unsigned lane = tid & 7;
    if (e >= N_EDGES) return;

    int s = g_src[e];
    int d = g_dst[e];
    float nd = __ldg(&g_dinv[d]);

    const float4 v = *(const float4*)(g_h1s + s * F1 + lane * 4);
    red_add_v4(g_agg1 + d * F1 + lane * 4,
               v.x * nd, v.y * nd, v.z * nd, v.w * nd);
}

// h = relu(agg1 + b1); h2 = h @ W2; h2s = h2*dinv; agg2 init = h2s*dinv
__global__ void k_layer2_node(const float* __restrict__ W2,
                              const float* __restrict__ b1) {
    __shared__ float sW[F1 * F2];
    __shared__ float sb[F1];
    for (int t = threadIdx.x; t < F1 * F2; t += blockDim.x) sW[t] = W2[t];
    for (int t = threadIdx.x; t < F1; t += blockDim.x) sb[t] = b1[t];
    __syncthreads();

    int i = blockIdx.x * blockDim.x + threadIdx.x;
    if (i >= N_NODES) return;

    float acc0 = 0.0f, acc1 = 0.0f, acc2 = 0.0f;
    const float4* ar = (const float4*)(g_agg1 + i * F1);
    #pragma unroll
    for (int q = 0; q < F1 / 4; q++) {
        float4 v = ar[q];
        float h0 = fmaxf(v.x + sb[4*q+0], 0.0f);
        float h1 = fmaxf(v.y + sb[4*q+1], 0.0f);
        float h2 = fmaxf(v.z + sb[4*q+2], 0.0f);
        float h3 = fmaxf(v.w + sb[4*q+3], 0.0f);
        acc0 = fmaf(h0, sW[(4*q+0)*F2+0], acc0);
        acc1 = fmaf(h0, sW[(4*q+0)*F2+1], acc1);
        acc2 = fmaf(h0, sW[(4*q+0)*F2+2], acc2);
        acc0 = fmaf(h1, sW[(4*q+1)*F2+0], acc0);
        acc1 = fmaf(h1, sW[(4*q+1)*F2+1], acc1);
        acc2 = fmaf(h1, sW[(4*q+1)*F2+2], acc2);
        acc0 = fmaf(h2, sW[(4*q+2)*F2+0], acc0);
        acc1 = fmaf(h2, sW[(4*q+2)*F2+1], acc1);
        acc2 = fmaf(h2, sW[(4*q+2)*F2+2], acc2);
        acc0 = fmaf(h3, sW[(4*q+3)*F2+0], acc0);
        acc1 = fmaf(h3, sW[(4*q+3)*F2+1], acc1);
        acc2 = fmaf(h3, sW[(4*q+3)*F2+2], acc2);
    }

    float di = g_dinv[i];
    g_h2s [i * F2 + 0] = acc0 * di;
    g_h2s [i * F2 + 1] = acc1 * di;
    g_h2s [i * F2 + 2] = acc2 * di;
    g_agg2[i * F2 + 0] = acc0 * di * di;
    g_agg2[i * F2 + 1] = acc1 * di * di;
    g_agg2[i * F2 + 2] = acc2 * di * di;
}

__global__ void k_edge2() {
    int e = blockIdx.x * blockDim.x + threadIdx.x;
    if (e >= N_EDGES) return;

    int s = g_src[e];
    int d = g_dst[e];
    float nd = __ldg(&g_dinv[d]);

    float m0 = __ldg(&g_h2s[s * F2 + 0]) * nd;
    float m1 = __ldg(&g_h2s[s * F2 + 1]) * nd;
    float m2 = __ldg(&g_h2s[s * F2 + 2]) * nd;
    atomicAdd(&g_agg2[d * F2 + 0], m0);
    atomicAdd(&g_agg2[d * F2 + 1], m1);
    atomicAdd(&g_agg2[d * F2 + 2], m2);
}

__global__ void k_logsoftmax(const float* __restrict__ b2,
                             float* __restrict__ out) {
    int i = blockIdx.x * blockDim.x + threadIdx.x;
    if (i >= N_NODES) return;
    float v0 = g_agg2[i * F2 + 0] + b2[0];
    float v1 = g_agg2[i * F2 + 1] + b2[1];
    float v2 = g_agg2[i * F2 + 2] + b2[2];
    float m = fmaxf(v0, fmaxf(v1, v2));
    float l = logf(expf(v0 - m) + expf(v1 - m) + expf(v2 - m));
    out[i * F2 + 0] = v0 - m - l;
    out[i * F2 + 1] = v1 - m - l;
    out[i * F2 + 2] = v2 - m - l;
}

// ---------------- launch ----------------

extern "C" void kernel_launch(void* const* d_in, const int* in_sizes, int n_in,
                              void* d_out, int out_size) {
    const float* x  = (const float*)d_in[0];
    const void*  ei = d_in[1];                 // [2, E] int32 or int64
    const float* W1 = (const float*)d_in[2];
    const float* b1 = (const float*)d_in[3];
    const float* W2 = (const float*)d_in[4];
    const float* b2 = (const float*)d_in[5];
    float*       out = (float*)d_out;

    const int T = 256;
    const int gN  = (N_NODES + T - 1) / T;
    const int gE  = (N_EDGES + T - 1) / T;
    const int gE8 = (N_EDGES * 8 + T - 1) / T;

    k_detect     <<<1, 32>>>((const int*)ei);
    k_convert    <<<gE, T>>>(ei);
    k_init_deg   <<<gN, T>>>();
    k_count_deg  <<<gE, T>>>();
    k_dinv       <<<gN, T>>>();
    k_layer1_node<<<gN, T>>>(x, W1);
    k_edge1      <<<gE8, T>>>();
    k_layer2_node<<<gN, T>>>(W2, b1);
    k_edge2      <<<gE, T>>>();
    k_logsoftmax <<<gN, T>>>(b2, out);
}

// round 4
// speedup vs baseline: 1.3339x; 1.3339x over previous
#include <cuda_runtime.h>
#include <cstdint>

#define N_NODES 100000
#define N_EDGES 3200000
#define F0 16
#define F1 32
#define F2 3

// ---------------- scratch (no allocations allowed) ----------------
__device__ int g_is64;
__device__ __align__(16) static int2  g_edge[N_EDGES];       // (src, dst)
__device__ __align__(16) static float g_deg [N_NODES];
__device__ __align__(16) static float g_dinv[N_NODES];
__device__ __align__(16) static float g_h1s [N_NODES * F1];  // h1 * dinv[src]
__device__ __align__(16) static float g_agg1[N_NODES * F1];
__device__ __align__(16) static float g_h2s4[N_NODES * 4];   // h2 * dinv, padded
__device__ __align__(16) static float g_agg2[N_NODES * 4];

// ---------------- dtype detect ----------------
// int64 node ids < 2^31 => odd 32-bit words all zero over 128 samples.
__global__ void k_detect(const int* __restrict__ ei32) {
    if (threadIdx.x == 0) {
        int any_nonzero = 0;
        for (int k = 0; k < 128; k++) any_nonzero |= ei32[2 * k + 1];
        g_is64 = (any_nonzero == 0) ? 1 : 0;
    }
}

__global__ void k_init_deg() {
    int i = blockIdx.x * blockDim.x + threadIdx.x;
    if (i < N_NODES) g_deg[i] = 1.0f;  // self-loop
}

// convert edge list to int2 AND count degrees in the same pass
__global__ void k_convert_count(const void* __restrict__ ei) {
    int e = blockIdx.x * blockDim.x + threadIdx.x;
    if (e >= N_EDGES) return;
    int s, d;
    if (g_is64) {
        const long long* p = (const long long*)ei;
        s = (int)p[e];
        d = (int)p[N_EDGES + e];
    } else {
        const int* p = (const int*)ei;
        s = p[e];
        d = p[N_EDGES + e];
    }
    g_edge[e] = make_int2(s, d);
    atomicAdd(&g_deg[d], 1.0f);  // result unused -> RED
}

// h1 = x @ W1 ; dinv = rsqrt(deg) ; h1s = h1*dinv ; agg1 init = h1s (self-loop)
__global__ void k_layer1_node(const float* __restrict__ x,
                              const float* __restrict__ W1) {
    __shared__ float sW[F0 * F1];
    for (int t = threadIdx.x; t < F0 * F1; t += blockDim.x) sW[t] = W1[t];
    __syncthreads();

    int i = blockIdx.x * blockDim.x + threadIdx.x;
    if (i >= N_NODES) return;

    float xv[F0];
    const float4* xr = (const float4*)(x + i * F0);
    #pragma unroll
    for (int k = 0; k < F0 / 4; k++) {
        float4 v = xr[k];
        xv[4*k+0] = v.x; xv[4*k+1] = v.y; xv[4*k+2] = v.z; xv[4*k+3] = v.w;
    }

    float acc[F1];
    #pragma unroll
    for (int j = 0; j < F1; j++) acc[j] = 0.0f;
    #pragma unroll
    for (int k = 0; k < F0; k++) {
        float xk = xv[k];
        #pragma unroll
        for (int j = 0; j < F1; j++) acc[j] = fmaf(xk, sW[k * F1 + j], acc[j]);
    }

    float di = rsqrtf(g_deg[i]);
    g_dinv[i] = di;

    float4* h1s  = (float4*)(g_h1s  + i * F1);
    float4* agg1 = (float4*)(g_agg1 + i * F1);
    #pragma unroll
    for (int j = 0; j < F1 / 4; j++) {
        float4 s;
        s.x = acc[4*j+0] * di; s.y = acc[4*j+1] * di;
        s.z = acc[4*j+2] * di; s.w = acc[4*j+3] * di;
        h1s[j]  = s;
        agg1[j] = s;   // self-loop term (dinv[d] applied later per-node)
    }
}

__device__ __forceinline__ void red_add_v4(float* p, float a, float b, float c, float d) {
    asm volatile(
        "{\n\t"
        ".reg .u64 pg;\n\t"
        "cvta.to.global.u64 pg, %0;\n\t"
        "red.global.add.v4.f32 [pg], {%1, %2, %3, %4};\n\t"
        "}"
        :: "l"(p), "f"(a), "f"(b), "f"(c), "f"(d)
        : "memory");
}

// 8 lanes per edge: pure gather + vector reduction (no per-edge scaling)
__global__ void k_edge1() {
    unsigned tid = blockIdx.x * blockDim.x + threadIdx.x;
    unsigned e = tid >> 3;
    unsigned lane = tid & 7;
    if (e >= N_EDGES) return;

    int2 ed = g_edge[e];
    const float4 v = *(const float4*)(g_h1s + ed.x * F1 + lane * 4);
    red_add_v4(g_agg1 + ed.y * F1 + lane * 4, v.x, v.y, v.z, v.w);
}

// h = relu(dinv*agg1 + b1); h2 = h @ W2; h2s4 = h2*dinv (pad); agg2 init = h2s4
__global__ void k_layer2_node(const float* __restrict__ W2,
                              const float* __restrict__ b1) {
    __shared__ float sW[F1 * F2];
    __shared__ float sb[F1];
    for (int t = threadIdx.x; t < F1 * F2; t += blockDim.x) sW[t] = W2[t];
    for (int t = threadIdx.x; t < F1; t += blockDim.x) sb[t] = b1[t];
    __syncthreads();

    int i = blockIdx.x * blockDim.x + threadIdx.x;
    if (i >= N_NODES) return;

    float di = g_dinv[i];
    float acc0 = 0.0f, acc1 = 0.0f, acc2 = 0.0f;
    const float4* ar = (const float4*)(g_agg1 + i * F1);
    #pragma unroll
    for (int q = 0; q < F1 / 4; q++) {
        float4 v = ar[q];
        float h0 = fmaxf(fmaf(v.x, di, sb[4*q+0]), 0.0f);
        float h1 = fmaxf(fmaf(v.y, di, sb[4*q+1]), 0.0f);
        float h2 = fmaxf(fmaf(v.z, di, sb[4*q+2]), 0.0f);
        float h3 = fmaxf(fmaf(v.w, di, sb[4*q+3]), 0.0f);
        acc0 = fmaf(h0, sW[(4*q+0)*F2+0], acc0);
        acc1 = fmaf(h0, sW[(4*q+0)*F2+1], acc1);
        acc2 = fmaf(h0, sW[(4*q+0)*F2+2], acc2);
        acc0 = fmaf(h1, sW[(4*q+1)*F2+0], acc0);
        acc1 = fmaf(h1, sW[(4*q+1)*F2+1], acc1);
        acc2 = fmaf(h1, sW[(4*q+1)*F2+2], acc2);
        acc0 = fmaf(h2, sW[(4*q+2)*F2+0], acc0);
        acc1 = fmaf(h2, sW[(4*q+2)*F2+1], acc1);
        acc2 = fmaf(h2, sW[(4*q+2)*F2+2], acc2);
        acc0 = fmaf(h3, sW[(4*q+3)*F2+0], acc0);
        acc1 = fmaf(h3, sW[(4*q+3)*F2+1], acc1);
        acc2 = fmaf(h3, sW[(4*q+3)*F2+2], acc2);
    }

    float4 h2s;
    h2s.x = acc0 * di; h2s.y = acc1 * di; h2s.z = acc2 * di; h2s.w = 0.0f;
    ((float4*)g_h2s4)[i] = h2s;
    ((float4*)g_agg2)[i] = h2s;   // self-loop term
}

// one thread per edge: float4 gather + single red.v4
__global__ void k_edge2() {
    int e = blockIdx.x * blockDim.x + threadIdx.x;
    if (e >= N_EDGES) return;
    int2 ed = g_edge[e];
    const float4 v = ((const float4*)g_h2s4)[ed.x];
    red_add_v4(g_agg2 + ed.y * 4, v.x, v.y, v.z, v.w);
}

__global__ void k_logsoftmax(const float* __restrict__ b2,
                             float* __restrict__ out) {
    int i = blockIdx.x * blockDim.x + threadIdx.x;
    if (i >= N_NODES) return;
    float di = g_dinv[i];
    float4 a = ((const float4*)g_agg2)[i];
    float v0 = fmaf(a.x, di, b2[0]);
    float v1 = fmaf(a.y, di, b2[1]);
    float v2 = fmaf(a.z, di, b2[2]);
    float m = fmaxf(v0, fmaxf(v1, v2));
    float l = logf(expf(v0 - m) + expf(v1 - m) + expf(v2 - m));
    out[i * F2 + 0] = v0 - m - l;
    out[i * F2 + 1] = v1 - m - l;
    out[i * F2 + 2] = v2 - m - l;
}

// ---------------- launch ----------------

extern "C" void kernel_launch(void* const* d_in, const int* in_sizes, int n_in,
                              void* d_out, int out_size) {
    const float* x  = (const float*)d_in[0];
    const void*  ei = d_in[1];                 // [2, E] int32 or int64
    const float* W1 = (const float*)d_in[2];
    const float* b1 = (const float*)d_in[3];
    const float* W2 = (const float*)d_in[4];
    const float* b2 = (const float*)d_in[5];
    float*       out = (float*)d_out;

    const int T = 256;
    const int gN  = (N_NODES + T - 1) / T;
    const int gE  = (N_EDGES + T - 1) / T;
    const int gE8 = (N_EDGES * 8 + T - 1) / T;

    k_detect       <<<1, 32>>>((const int*)ei);
    k_init_deg     <<<gN, T>>>();
    k_convert_count<<<gE, T>>>(ei);
    k_layer1_node  <<<gN, T>>>(x, W1);
    k_edge1        <<<gE8, T>>>();
    k_layer2_node  <<<gN, T>>>(W2, b1);
    k_edge2        <<<gE, T>>>();
    k_logsoftmax   <<<gN, T>>>(b2, out);
}

// round 6
// speedup vs baseline: 1.4684x; 1.1009x over previous
#include <cuda_runtime.h>
#include <cstdint>

#define N_NODES 100000
#define N_EDGES 3200000
#define F0 16
#define F1 32
#define F2 3
#define SCAN_T 256
#define NBLK ((N_NODES + SCAN_T - 1) / SCAN_T)   // 391

// ---------------- scratch (no allocations allowed) ----------------
__device__ int g_is64;
__device__ static int   g_count[N_NODES];     // incoming-edge count (no self loop)
__device__ static int   g_row  [N_NODES];     // CSR row start (exclusive prefix)
__device__ static int   g_fill [N_NODES];     // scatter cursor
__device__ static int   g_bsum [NBLK + 1];
__device__ static int   g_csr  [N_EDGES];     // src ids grouped by dst
__device__ __align__(16) static float g_dinv[N_NODES];
__device__ __align__(16) static float g_h1s [N_NODES * F1];  // h1 * dinv
__device__ __align__(16) static float g_h2s4[N_NODES * 4];   // h2 * dinv, padded

// ---------------- dtype detect ----------------
__global__ void k_detect(const int* __restrict__ ei32) {
    if (threadIdx.x == 0) {
        int any_nonzero = 0;
        for (int k = 0; k < 128; k++) any_nonzero |= ei32[2 * k + 1];
        g_is64 = (any_nonzero == 0) ? 1 : 0;
    }
}

__global__ void k_zero_count() {
    int i = blockIdx.x * blockDim.x + threadIdx.x;
    if (i < N_NODES) g_count[i] = 0;
}

__global__ void k_count(const void* __restrict__ ei) {
    int e = blockIdx.x * blockDim.x + threadIdx.x;
    if (e >= N_EDGES) return;
    int d = g_is64 ? (int)((const long long*)ei)[N_EDGES + e]
                   : ((const int*)ei)[N_EDGES + e];
    atomicAdd(&g_count[d], 1);   // result unused -> RED
}

// block-level inclusive scan -> exclusive per-element + block sums
__global__ void k_scanA() {
    __shared__ int s[SCAN_T];
    int i = blockIdx.x * SCAN_T + threadIdx.x;
    int v = (i < N_NODES) ? g_count[i] : 0;
    s[threadIdx.x] = v;
    __syncthreads();
    #pragma unroll
    for (int off = 1; off < SCAN_T; off <<= 1) {
        int a = (threadIdx.x >= off) ? s[threadIdx.x - off] : 0;
        __syncthreads();
        s[threadIdx.x] += a;
        __syncthreads();
    }
    if (i < N_NODES) g_row[i] = s[threadIdx.x] - v;   // block-local exclusive
    if (threadIdx.x == SCAN_T - 1) g_bsum[blockIdx.x] = s[SCAN_T - 1];
}

__global__ void k_scanB() {   // 1 block, 512 threads, scan NBLK block sums
    __shared__ int s[512];
    int t = threadIdx.x;
    int v = (t < NBLK) ? g_bsum[t] : 0;
    s[t] = v;
    __syncthreads();
    #pragma unroll
    for (int off = 1; off < 512; off <<= 1) {
        int a = (t >= off) ? s[t - off] : 0;
        __syncthreads();
        s[t] += a;
        __syncthreads();
    }
    if (t < NBLK) g_bsum[t] = s[t] - v;   // exclusive
}

// launched with SCAN_T threads/block, NBLK blocks: one block per scanA block
__global__ void k_scanC() {
    int i = blockIdx.x * SCAN_T + threadIdx.x;
    if (i >= N_NODES) return;
    int r = g_row[i] + g_bsum[blockIdx.x];
    g_row[i]  = r;
    g_fill[i] = r;
    g_dinv[i] = rsqrtf((float)(g_count[i] + 1));   // +1 self loop
}

__global__ void k_scatter(const void* __restrict__ ei) {
    int e = blockIdx.x * blockDim.x + threadIdx.x;
    if (e >= N_EDGES) return;
    int s, d;
    if (g_is64) {
        const long long* p = (const long long*)ei;
        s = (int)p[e];  d = (int)p[N_EDGES + e];
    } else {
        const int* p = (const int*)ei;
        s = p[e];       d = p[N_EDGES + e];
    }
    int slot = atomicAdd(&g_fill[d], 1);
    g_csr[slot] = s;
}

// h1 = x @ W1 ; h1s = h1 * dinv
__global__ void k_layer1_node(const float* __restrict__ x,
                              const float* __restrict__ W1) {
    __shared__ float sW[F0 * F1];
    for (int t = threadIdx.x; t < F0 * F1; t += blockDim.x) sW[t] = W1[t];
    __syncthreads();

    int i = blockIdx.x * blockDim.x + threadIdx.x;
    if (i >= N_NODES) return;

    float xv[F0];
    const float4* xr = (const float4*)(x + i * F0);
    #pragma unroll
    for (int k = 0; k < F0 / 4; k++) {
        float4 v = xr[k];
        xv[4*k+0] = v.x; xv[4*k+1] = v.y; xv[4*k+2] = v.z; xv[4*k+3] = v.w;
    }

    float acc[F1];
    #pragma unroll
    for (int j = 0; j < F1; j++) acc[j] = 0.0f;
    #pragma unroll
    for (int k = 0; k < F0; k++) {
        float xk = xv[k];
        #pragma unroll
        for (int j = 0; j < F1; j++) acc[j] = fmaf(xk, sW[k * F1 + j], acc[j]);
    }

    float di = g_dinv[i];
    float4* h1s = (float4*)(g_h1s + i * F1);
    #pragma unroll
    for (int j = 0; j < F1 / 4; j++) {
        float4 s;
        s.x = acc[4*j+0] * di; s.y = acc[4*j+1] * di;
        s.z = acc[4*j+2] * di; s.w = acc[4*j+3] * di;
        h1s[j] = s;
    }
}

// warp per node: pull-aggregate h1s over incoming edges (coalesced, no atomics),
// then fuse layer 2: relu(di*acc + b1) @ W2, scale by di, write h2s4.
__global__ void k_agg1_fused(const float* __restrict__ W2,
                             const float* __restrict__ b1) {
    int warp = (blockIdx.x * blockDim.x + threadIdx.x) >> 5;
    int lane = threadIdx.x & 31;
    if (warp >= N_NODES) return;
    int i = warp;

    int row = g_row[i];
    int cnt = g_count[i];
    float di = g_dinv[i];

    // per-lane feature accumulation; init with self-loop term h1s[i]
    float acc = g_h1s[i * F1 + lane];

    int k = 0;
    for (; k + 4 <= cnt; k += 4) {
        int s0 = g_csr[row + k + 0];
        int s1 = g_csr[row + k + 1];
        int s2 = g_csr[row + k + 2];
        int s3 = g_csr[row + k + 3];
        float v0 = g_h1s[s0 * F1 + lane];
        float v1 = g_h1s[s1 * F1 + lane];
        float v2 = g_h1s[s2 * F1 + lane];
        float v3 = g_h1s[s3 * F1 + lane];
        acc += (v0 + v1) + (v2 + v3);
    }
    for (; k < cnt; k++)
        acc += g_h1s[g_csr[row + k] * F1 + lane];

    // layer 2: h = relu(di*acc + b1[lane]); partials p_n = h * W2[lane][n]
    float h = fmaxf(fmaf(di, acc, __ldg(&b1[lane])), 0.0f);
    float p0 = h * __ldg(&W2[lane * F2 + 0]);
    float p1 = h * __ldg(&W2[lane * F2 + 1]);
    float p2 = h * __ldg(&W2[lane * F2 + 2]);
    #pragma unroll
    for (int off = 16; off > 0; off >>= 1) {
        p0 += __shfl_down_sync(0xFFFFFFFFu, p0, off);
        p1 += __shfl_down_sync(0xFFFFFFFFu, p1, off);
        p2 += __shfl_down_sync(0xFFFFFFFFu, p2, off);
    }
    if (lane == 0) {
        float4 o;
        o.x = p0 * di; o.y = p1 * di; o.z = p2 * di; o.w = 0.0f;
        ((float4*)g_h2s4)[i] = o;
    }
}

// thread per node: aggregate h2s4 over incoming edges + self, bias, log_softmax
__global__ void k_agg2_fused(const float* __restrict__ b2,
                             float* __restrict__ out) {
    int i = blockIdx.x * blockDim.x + threadIdx.x;
    if (i >= N_NODES) return;

    int row = g_row[i];
    int cnt = g_count[i];
    float di = g_dinv[i];

    float4 self = ((const float4*)g_h2s4)[i];
    float a0 = self.x, a1 = self.y, a2 = self.z;

    int k = 0;
    for (; k + 4 <= cnt; k += 4) {
        int s0 = g_csr[row + k + 0];
        int s1 = g_csr[row + k + 1];
        int s2 = g_csr[row + k + 2];
        int s3 = g_csr[row + k + 3];
        float4 v0 = ((const float4*)g_h2s4)[s0];
        float4 v1 = ((const float4*)g_h2s4)[s1];
        float4 v2 = ((const float4*)g_h2s4)[s2];
        float4 v3 = ((const float4*)g_h2s4)[s3];
        a0 += (v0.x + v1.x) + (v2.x + v3.x);
        a1 += (v0.y + v1.y) + (v2.y + v3.y);
        a2 += (v0.z + v1.z) + (v2.z + v3.z);
    }
    for (; k < cnt; k++) {
        float4 v = ((const float4*)g_h2s4)[g_csr[row + k]];
        a0 += v.x; a1 += v.y; a2 += v.z;
    }

    float v0 = fmaf(a0, di, __ldg(&b2[0]));
    float v1 = fmaf(a1, di, __ldg(&b2[1]));
    float v2 = fmaf(a2, di, __ldg(&b2[2]));
    float m = fmaxf(v0, fmaxf(v1, v2));
    float l = logf(expf(v0 - m) + expf(v1 - m) + expf(v2 - m));
    out[i * F2 + 0] = v0 - m - l;
    out[i * F2 + 1] = v1 - m - l;
    out[i * F2 + 2] = v2 - m - l;
}

// ---------------- launch ----------------

extern "C" void kernel_launch(void* const* d_in, const int* in_sizes, int n_in,
                              void* d_out, int out_size) {
    const float* x  = (const float*)d_in[0];
    const void*  ei = d_in[1];                 // [2, E] int32 or int64
    const float* W1 = (const float*)d_in[2];
    const float* b1 = (const float*)d_in[3];
    const float* W2 = (const float*)d_in[4];
    const float* b2 = (const float*)d_in[5];
    float*       out = (float*)d_out;

    const int T = 256;
    const int gN = (N_NODES + T - 1) / T;               // 391
    const int gE = (N_EDGES + T - 1) / T;               // 12500
    const int gW = (N_NODES * 32 + T - 1) / T;          // warp per node

    k_detect     <<<1, 32>>>((const int*)ei);
    k_zero_count <<<gN, T>>>();
    k_count      <<<gE, T>>>(ei);
    k_scanA      <<<NBLK, SCAN_T>>>();
    k_scanB      <<<1, 512>>>();
    k_scanC      <<<NBLK, SCAN_T>>>();
    k_scatter    <<<gE, T>>>(ei);
    k_layer1_node<<<gN, T>>>(x, W1);
    k_agg1_fused <<<gW, T>>>(W2, b1);
    k_agg2_fused <<<gN, T>>>(b2, out);
}

// round 7
// speedup vs baseline: 1.6081x; 1.0951x over previous
#include <cuda_runtime.h>
#include <cuda_fp16.h>
#include <cstdint>

#define N_NODES 100000
#define N_EDGES 3200000
#define F0 16
#define F1 32
#define F2 3
#define SCAN_T 256
#define NBLK ((N_NODES + SCAN_T - 1) / SCAN_T)   // 391

// ---------------- scratch (no allocations allowed) ----------------
__device__ int g_is64;
__device__ static int   g_count[N_NODES];
__device__ static int   g_row  [N_NODES];
__device__ static int   g_fill [N_NODES];
__device__ static int   g_bsum [NBLK + 1];
__device__ static int   g_csr  [N_EDGES];
__device__ __align__(16) static float  g_dinv[N_NODES];
__device__ __align__(16) static __half g_h1sh[N_NODES * F1];  // h1 * dinv, fp16
__device__ __align__(16) static float  g_h2s4[N_NODES * 4];   // h2 * dinv, padded

// ---------------- zero + dtype detect (fused) ----------------
__global__ void k_zero_detect(const int* __restrict__ ei32) {
    int i = blockIdx.x * blockDim.x + threadIdx.x;
    if (i < N_NODES) g_count[i] = 0;
    if (i == 0) {
        int any_nonzero = 0;
        for (int k = 0; k < 128; k++) any_nonzero |= ei32[2 * k + 1];
        g_is64 = (any_nonzero == 0) ? 1 : 0;
    }
}

__global__ void k_count(const void* __restrict__ ei) {
    int e = blockIdx.x * blockDim.x + threadIdx.x;
    if (e >= N_EDGES) return;
    int d = g_is64 ? (int)((const long long*)ei)[N_EDGES + e]
                   : ((const int*)ei)[N_EDGES + e];
    atomicAdd(&g_count[d], 1);   // result unused -> RED
}

__global__ void k_scanA() {
    __shared__ int s[SCAN_T];
    int i = blockIdx.x * SCAN_T + threadIdx.x;
    int v = (i < N_NODES) ? g_count[i] : 0;
    s[threadIdx.x] = v;
    __syncthreads();
    #pragma unroll
    for (int off = 1; off < SCAN_T; off <<= 1) {
        int a = (threadIdx.x >= off) ? s[threadIdx.x - off] : 0;
        __syncthreads();
        s[threadIdx.x] += a;
        __syncthreads();
    }
    if (i < N_NODES) g_row[i] = s[threadIdx.x] - v;
    if (threadIdx.x == SCAN_T - 1) g_bsum[blockIdx.x] = s[SCAN_T - 1];
}

__global__ void k_scanB() {
    __shared__ int s[512];
    int t = threadIdx.x;
    int v = (t < NBLK) ? g_bsum[t] : 0;
    s[t] = v;
    __syncthreads();
    #pragma unroll
    for (int off = 1; off < 512; off <<= 1) {
        int a = (t >= off) ? s[t - off] : 0;
        __syncthreads();
        s[t] += a;
        __syncthreads();
    }
    if (t < NBLK) g_bsum[t] = s[t] - v;
}

__global__ void k_scanC() {
    int i = blockIdx.x * SCAN_T + threadIdx.x;
    if (i >= N_NODES) return;
    int r = g_row[i] + g_bsum[blockIdx.x];
    g_row[i]  = r;
    g_fill[i] = r;
    g_dinv[i] = rsqrtf((float)(g_count[i] + 1));
}

__global__ void k_scatter(const void* __restrict__ ei) {
    int e = blockIdx.x * blockDim.x + threadIdx.x;
    if (e >= N_EDGES) return;
    int s, d;
    if (g_is64) {
        const long long* p = (const long long*)ei;
        s = (int)p[e];  d = (int)p[N_EDGES + e];
    } else {
        const int* p = (const int*)ei;
        s = p[e];       d = p[N_EDGES + e];
    }
    int slot = atomicAdd(&g_fill[d], 1);
    g_csr[slot] = s;
}

// 2 threads per node, 16 output features each; fp16 output
__global__ void k_layer1_node(const float* __restrict__ x,
                              const float* __restrict__ W1) {
    __shared__ float sW[F0 * F1];
    for (int t = threadIdx.x; t < F0 * F1; t += blockDim.x) sW[t] = W1[t];
    __syncthreads();

    int t = blockIdx.x * blockDim.x + threadIdx.x;
    int i = t >> 1;
    int hsel = t & 1;          // which 16 of the 32 outputs
    if (i >= N_NODES) return;

    float xv[F0];
    const float4* xr = (const float4*)(x + i * F0);
    #pragma unroll
    for (int k = 0; k < F0 / 4; k++) {
        float4 v = xr[k];
        xv[4*k+0] = v.x; xv[4*k+1] = v.y; xv[4*k+2] = v.z; xv[4*k+3] = v.w;
    }

    float acc[16];
    #pragma unroll
    for (int j = 0; j < 16; j++) acc[j] = 0.0f;
    const float* wbase = sW + hsel * 16;
    #pragma unroll
    for (int k = 0; k < F0; k++) {
        float xk = xv[k];
        #pragma unroll
        for (int j = 0; j < 16; j++) acc[j] = fmaf(xk, wbase[k * F1 + j], acc[j]);
    }

    float di = g_dinv[i];
    __half2 o[8];
    #pragma unroll
    for (int j = 0; j < 8; j++)
        o[j] = __floats2half2_rn(acc[2*j] * di, acc[2*j+1] * di);
    // 16 halves = 32B = two uint4 stores
    uint4* dst = (uint4*)(g_h1sh + i * F1 + hsel * 16);
    dst[0] = *(const uint4*)&o[0];
    dst[1] = *(const uint4*)&o[4];
}

// warp per node: half-warps process even/odd edges; lane&15 owns a half2 pair.
// Pull-aggregate in fp32, then fused layer2 + write h2s4.
__global__ void k_agg1_fused(const float* __restrict__ W2,
                             const float* __restrict__ b1) {
    int warp = (blockIdx.x * blockDim.x + threadIdx.x) >> 5;
    int lane = threadIdx.x & 31;
    if (warp >= N_NODES) return;
    int i = warp;

    int row = g_row[i];
    int cnt = g_count[i];
    float di = g_dinv[i];
    int grp = lane >> 4;       // 0: even edges (+self), 1: odd edges
    int j   = lane & 15;       // feature-pair index

    const __half2* h1 = (const __half2*)g_h1sh;

    float2 acc = make_float2(0.0f, 0.0f);
    if (grp == 0)
        acc = __half22float2(h1[i * 16 + j]);   // self-loop

    for (int k = grp; k < cnt; k += 2) {
        int s = g_csr[row + k];
        float2 f = __half22float2(h1[s * 16 + j]);
        acc.x += f.x; acc.y += f.y;
    }
    // combine even/odd groups (both halves end with the full sum)
    acc.x += __shfl_xor_sync(0xFFFFFFFFu, acc.x, 16);
    acc.y += __shfl_xor_sync(0xFFFFFFFFu, acc.y, 16);

    // layer2: features 2j, 2j+1
    float h0 = fmaxf(fmaf(di, acc.x, __ldg(&b1[2*j])),   0.0f);
    float h1v = fmaxf(fmaf(di, acc.y, __ldg(&b1[2*j+1])), 0.0f);
    float p0 = h0 * __ldg(&W2[(2*j)*F2+0]) + h1v * __ldg(&W2[(2*j+1)*F2+0]);
    float p1 = h0 * __ldg(&W2[(2*j)*F2+1]) + h1v * __ldg(&W2[(2*j+1)*F2+1]);
    float p2 = h0 * __ldg(&W2[(2*j)*F2+2]) + h1v * __ldg(&W2[(2*j+1)*F2+2]);
    #pragma unroll
    for (int off = 8; off > 0; off >>= 1) {
        p0 += __shfl_xor_sync(0xFFFFFFFFu, p0, off);
        p1 += __shfl_xor_sync(0xFFFFFFFFu, p1, off);
        p2 += __shfl_xor_sync(0xFFFFFFFFu, p2, off);
    }
    if (lane == 0) {
        float4 o;
        o.x = p0 * di; o.y = p1 * di; o.z = p2 * di; o.w = 0.0f;
        ((float4*)g_h2s4)[i] = o;
    }
}

// thread per node: aggregate h2s4 + self, bias, log_softmax
__global__ void k_agg2_fused(const float* __restrict__ b2,
                             float* __restrict__ out) {
    int i = blockIdx.x * blockDim.x + threadIdx.x;
    if (i >= N_NODES) return;

    int row = g_row[i];
    int cnt = g_count[i];
    float di = g_dinv[i];

    float4 self = ((const float4*)g_h2s4)[i];
    float a0 = self.x, a1 = self.y, a2 = self.z;

    int k = 0;
    for (; k + 4 <= cnt; k += 4) {
        int s0 = g_csr[row + k + 0];
        int s1 = g_csr[row + k + 1];
        int s2 = g_csr[row + k + 2];
        int s3 = g_csr[row + k + 3];
        float4 v0 = ((const float4*)g_h2s4)[s0];
        float4 v1 = ((const float4*)g_h2s4)[s1];
        float4 v2 = ((const float4*)g_h2s4)[s2];
        float4 v3 = ((const float4*)g_h2s4)[s3];
        a0 += (v0.x + v1.x) + (v2.x + v3.x);
        a1 += (v0.y + v1.y) + (v2.y + v3.y);
        a2 += (v0.z + v1.z) + (v2.z + v3.z);
    }
    for (; k < cnt; k++) {
        float4 v = ((const float4*)g_h2s4)[g_csr[row + k]];
        a0 += v.x; a1 += v.y; a2 += v.z;
    }

    float v0 = fmaf(a0, di, __ldg(&b2[0]));
    float v1 = fmaf(a1, di, __ldg(&b2[1]));
    float v2 = fmaf(a2, di, __ldg(&b2[2]));
    float m = fmaxf(v0, fmaxf(v1, v2));
    float l = logf(expf(v0 - m) + expf(v1 - m) + expf(v2 - m));
    out[i * F2 + 0] = v0 - m - l;
    out[i * F2 + 1] = v1 - m - l;
    out[i * F2 + 2] = v2 - m - l;
}

// ---------------- launch ----------------

extern "C" void kernel_launch(void* const* d_in, const int* in_sizes, int n_in,
                              void* d_out, int out_size) {
    const float* x  = (const float*)d_in[0];
    const void*  ei = d_in[1];
    const float* W1 = (const float*)d_in[2];
    const float* b1 = (const float*)d_in[3];
    const float* W2 = (const float*)d_in[4];
    const float* b2 = (const float*)d_in[5];
    float*       out = (float*)d_out;

    const int T = 256;
    const int gN  = (N_NODES + T - 1) / T;              // 391
    const int gN2 = (N_NODES * 2 + T - 1) / T;          // 782
    const int gE  = (N_EDGES + T - 1) / T;              // 12500
    const int gW  = (N_NODES * 32 + T - 1) / T;         // warp per node

    k_zero_detect<<<gN, T>>>((const int*)ei);
    k_count      <<<gE, T>>>(ei);
    k_scanA      <<<NBLK, SCAN_T>>>();
    k_scanB      <<<1, 512>>>();
    k_scanC      <<<NBLK, SCAN_T>>>();
    k_scatter    <<<gE, T>>>(ei);
    k_layer1_node<<<gN2, T>>>(x, W1);
    k_agg1_fused <<<gW, T>>>(W2, b1);
    k_agg2_fused <<<gN, T>>>(b2, out);
}